// round 6
// baseline (speedup 1.0000x reference)
#include <cuda_runtime.h>
#include <cuda_fp16.h>
#include <stdint.h>

#define NUM_SEGMENTS 4480
#define ATOM_DIM 64
#define BOND_DIM 16
#define N_EDGES 65536
#define NCOLS 1088   // 16*64 kernel-projected cols + 64 bias cols

// Scratch: per-atom projected features in fp16.
__device__ __half g_Yh[(size_t)NUM_SEGMENTS * NCOLS];

typedef unsigned long long u64;

// ---- packed f32x2 helpers (FFMA2 only reachable via PTX) ----
__device__ __forceinline__ u64 pack2(float lo, float hi) {
    u64 r; asm("mov.b64 %0, {%1, %2};" : "=l"(r) : "f"(lo), "f"(hi)); return r;
}
__device__ __forceinline__ void unpack2(float& lo, float& hi, u64 v) {
    asm("mov.b64 {%0, %1}, %2;" : "=f"(lo), "=f"(hi) : "l"(v));
}
__device__ __forceinline__ void ffma2(u64& d, u64 a, u64 b) {
    asm("fma.rn.f32x2 %0, %1, %2, %0;" : "+l"(d) : "l"(a), "l"(b));
}

// Dynamic smem layout (100352 B total):
//   APr[64][66]  u64: A^T row-pairs, APr[k][rp] = (A[2rp][k], A[2rp+1][k]); stride 66 pairs
//   Wd [64][130] u64: duplicated col pairs, Wd[k][c] = (w,w); stride 130 pairs
#define APR_STRIDE 66
#define WD_STRIDE  130
#define APR_BYTES  (64 * APR_STRIDE * 8)                 // 33792
#define PROJ_SMEM  (APR_BYTES + 64 * WD_STRIDE * 8)     // 100352

// ---------------------------------------------------------------------------
// Phase 1: Y = atom (4480x64) @ W (64x1088) -> fp16, 128x128 tile, 8x8/thread,
// pure FFMA2 inner loop (6 LDS.128 + 32 FFMA2 per k). Zeroes `out` in y==0 blocks.
//   W[j][k*64+i]   = kernel[k*4096 + i*64 + j]
//   W[j][1024 + i] = bias[i*64 + j]
// ---------------------------------------------------------------------------
__global__ void __launch_bounds__(256, 2)
proj_kernel(const float* __restrict__ atom,
            const float* __restrict__ kern,
            const float* __restrict__ bias,
            float* __restrict__ out)
{
    extern __shared__ __align__(16) char smem_raw[];
    u64* APr = (u64*)smem_raw;
    u64* Wd  = (u64*)(smem_raw + APR_BYTES);

    const int a0 = blockIdx.x * 128;  // 35 blocks
    const int c0 = blockIdx.y * 128;  // 9 blocks (last covers cols 1024..1087)
    const int tid = threadIdx.x;

    if (blockIdx.y == 0) {
        float4* oz = (float4*)(out + (size_t)a0 * 64);
        // 128 rows * 64 cols = 8192 floats = 2048 float4
        #pragma unroll
        for (int t = 0; t < 8; t++)
            oz[tid + t * 256] = make_float4(0.f, 0.f, 0.f, 0.f);
    }

    // Fill A pairs (gmem coalesced in j)
    #pragma unroll
    for (int t = 0; t < 16; t++) {
        int idx = tid + t * 256;          // 4096 pairs
        int j = idx & 63, rp = idx >> 6;  // rp 0..63
        float x0 = atom[(a0 + 2 * rp)     * 64 + j];
        float x1 = atom[(a0 + 2 * rp + 1) * 64 + j];
        APr[j * APR_STRIDE + rp] = pack2(x0, x1);
    }
    // Fill W duplicated pairs (gmem coalesced in j)
    #pragma unroll
    for (int t = 0; t < 32; t++) {
        int idx = tid + t * 256;          // 8192 entries
        int j = idx & 63, c = idx >> 6;   // c 0..127
        int gc = c0 + c;
        float w = 0.f;
        if (gc < 1024)      { int kk = gc >> 6, i = gc & 63; w = kern[kk * 4096 + i * 64 + j]; }
        else if (gc < 1088) { w = bias[(gc - 1024) * 64 + j]; }
        Wd[j * WD_STRIDE + c] = pack2(w, w);
    }
    __syncthreads();

    const int tx = tid & 15;  // cols tx*8 .. +7
    const int ty = tid >> 4;  // rows ty*8 .. +7

    u64 acc[4][8] = {};       // acc[rp][c] packs rows (ty*8+2rp, ty*8+2rp+1)

    const u64* ap = APr + ty * 4;   // 4 row-pairs
    const u64* wp = Wd  + tx * 8;   // 8 dup col-pairs

    #pragma unroll 4
    for (int k = 0; k < 64; k++) {
        const ulonglong2 av0 = *(const ulonglong2*)(ap + k * APR_STRIDE);      // r01, r23
        const ulonglong2 av1 = *(const ulonglong2*)(ap + k * APR_STRIDE + 2);  // r45, r67
        const ulonglong2 wv0 = *(const ulonglong2*)(wp + k * WD_STRIDE);
        const ulonglong2 wv1 = *(const ulonglong2*)(wp + k * WD_STRIDE + 2);
        const ulonglong2 wv2 = *(const ulonglong2*)(wp + k * WD_STRIDE + 4);
        const ulonglong2 wv3 = *(const ulonglong2*)(wp + k * WD_STRIDE + 6);
        const u64 w[8] = {wv0.x, wv0.y, wv1.x, wv1.y, wv2.x, wv2.y, wv3.x, wv3.y};
        #pragma unroll
        for (int c = 0; c < 8; c++) {
            ffma2(acc[0][c], av0.x, w[c]);
            ffma2(acc[1][c], av0.y, w[c]);
            ffma2(acc[2][c], av1.x, w[c]);
            ffma2(acc[3][c], av1.y, w[c]);
        }
    }

    const int gc = c0 + tx * 8;
    if (gc < 1088) {
        #pragma unroll
        for (int rp = 0; rp < 4; rp++) {
            float lo[8], hi[8];
            #pragma unroll
            for (int c = 0; c < 8; c++) unpack2(lo[c], hi[c], acc[rp][c]);

            size_t r0 = (size_t)(a0 + ty * 8 + 2 * rp);
            __half2 l01 = __floats2half2_rn(lo[0], lo[1]);
            __half2 l23 = __floats2half2_rn(lo[2], lo[3]);
            __half2 l45 = __floats2half2_rn(lo[4], lo[5]);
            __half2 l67 = __floats2half2_rn(lo[6], lo[7]);
            *(uint4*)(g_Yh + r0 * NCOLS + gc) =
                make_uint4(*(uint32_t*)&l01, *(uint32_t*)&l23,
                           *(uint32_t*)&l45, *(uint32_t*)&l67);

            __half2 h01 = __floats2half2_rn(hi[0], hi[1]);
            __half2 h23 = __floats2half2_rn(hi[2], hi[3]);
            __half2 h45 = __floats2half2_rn(hi[4], hi[5]);
            __half2 h67 = __floats2half2_rn(hi[6], hi[7]);
            *(uint4*)(g_Yh + (r0 + 1) * NCOLS + gc) =
                make_uint4(*(uint32_t*)&h01, *(uint32_t*)&h23,
                           *(uint32_t*)&h45, *(uint32_t*)&h67);
        }
    }
}

// ---------------------------------------------------------------------------
// Phase 2: half-warp per edge (unchanged from R5; validated 14us).
// ---------------------------------------------------------------------------
__global__ void __launch_bounds__(256)
edge_kernel(const float* __restrict__ bond,
            const int* __restrict__ pair,
            float* __restrict__ out)
{
    const int warp = blockIdx.x * 8 + (threadIdx.x >> 5);
    const int half = (threadIdx.x >> 4) & 1;
    const int lid  = threadIdx.x & 15;
    const int e = warp * 2 + half;

    const int2 pr = ((const int2*)pair)[e];
    const int dst = pr.x;
    const int src = pr.y;

    const float4* __restrict__ bp = (const float4*)(bond + (size_t)e * 16);
    const float4 q0 = __ldg(bp + 0);
    const float4 q1 = __ldg(bp + 1);
    const float4 q2 = __ldg(bp + 2);
    const float4 q3 = __ldg(bp + 3);
    const float bk[16] = {q0.x, q0.y, q0.z, q0.w,
                          q1.x, q1.y, q1.z, q1.w,
                          q2.x, q2.y, q2.z, q2.w,
                          q3.x, q3.y, q3.z, q3.w};

    const __half* __restrict__ y = g_Yh + (size_t)src * NCOLS + 4 * lid;

    float m0, m1, m2, m3;
    {
        const uint2 v = *(const uint2*)(y + 1024);
        const float2 flo = __half22float2(*(const __half2*)&v.x);
        const float2 fhi = __half22float2(*(const __half2*)&v.y);
        m0 = flo.x; m1 = flo.y; m2 = fhi.x; m3 = fhi.y;
    }

    #pragma unroll
    for (int k = 0; k < 16; k++) {
        const uint2 v = *(const uint2*)(y + k * 64);
        const float2 flo = __half22float2(*(const __half2*)&v.x);
        const float2 fhi = __half22float2(*(const __half2*)&v.y);
        const float b = bk[k];
        m0 = fmaf(b, flo.x, m0);
        m1 = fmaf(b, flo.y, m1);
        m2 = fmaf(b, fhi.x, m2);
        m3 = fmaf(b, fhi.y, m3);
    }

    float* o = out + (size_t)dst * 64 + 4 * lid;
    asm volatile("red.global.add.v4.f32 [%0], {%1, %2, %3, %4};"
                 :: "l"(o), "f"(m0), "f"(m1), "f"(m2), "f"(m3)
                 : "memory");
}

extern "C" void kernel_launch(void* const* d_in, const int* in_sizes, int n_in,
                              void* d_out, int out_size)
{
    const float* atom = (const float*)d_in[0];      // [4480, 64]
    const float* bond = (const float*)d_in[1];      // [65536, 16]
    const int*   pair = (const int*)d_in[2];        // [65536, 2] int32
    const float* kern = (const float*)d_in[3];      // [16, 4096]
    const float* bias = (const float*)d_in[4];      // [4096]
    float*       out  = (float*)d_out;              // [4480, 64]

    (void)in_sizes; (void)n_in; (void)out_size;

    cudaFuncSetAttribute(proj_kernel,
                         cudaFuncAttributeMaxDynamicSharedMemorySize, PROJ_SMEM);

    dim3 grid1(NUM_SEGMENTS / 128, 9);  // (35, 9); y==0 blocks zero `out`
    proj_kernel<<<grid1, 256, PROJ_SMEM>>>(atom, kern, bias, out);

    edge_kernel<<<N_EDGES / 16, 256>>>(bond, pair, out);
}

// round 7
// speedup vs baseline: 3.0556x; 3.0556x over previous
#include <cuda_runtime.h>
#include <cuda_fp16.h>
#include <stdint.h>

#define NUM_SEGMENTS 4480
#define ATOM_DIM 64
#define BOND_DIM 16
#define N_EDGES 65536
#define NCOLS 1088   // 16*64 kernel-projected cols + 64 bias cols

// Scratch: per-atom projected features in fp16.
__device__ __half g_Yh[(size_t)NUM_SEGMENTS * NCOLS];

// ---- tensor-core helpers ----
__device__ __forceinline__ uint32_t smem_u32(const void* p) {
    return (uint32_t)__cvta_generic_to_shared(p);
}
__device__ __forceinline__ void ldm_x4(uint32_t& r0, uint32_t& r1,
                                       uint32_t& r2, uint32_t& r3, uint32_t addr) {
    asm volatile("ldmatrix.sync.aligned.m8n8.x4.shared.b16 {%0,%1,%2,%3}, [%4];"
                 : "=r"(r0), "=r"(r1), "=r"(r2), "=r"(r3) : "r"(addr));
}
__device__ __forceinline__ void mma16816(float* c,
                                         uint32_t a0, uint32_t a1, uint32_t a2, uint32_t a3,
                                         uint32_t b0, uint32_t b1) {
    asm volatile("mma.sync.aligned.m16n8k16.row.col.f32.f16.f16.f32 "
                 "{%0,%1,%2,%3}, {%4,%5,%6,%7}, {%8,%9}, {%0,%1,%2,%3};"
                 : "+f"(c[0]), "+f"(c[1]), "+f"(c[2]), "+f"(c[3])
                 : "r"(a0), "r"(a1), "r"(a2), "r"(a3), "r"(b0), "r"(b1));
}

#define AH_STRIDE 72   // halves per row (144 B, 16B-multiple, conflict-free for ldmatrix)
#define BS_STRIDE 72

// ---------------------------------------------------------------------------
// Phase 1 (tensor cores): Y = atom (4480x64) @ W (64x1088) -> fp16.
//   W[j][c] = kernel[(c>>6)*4096 + (c&63)*64 + j]  (c<1024)
//   W[j][1024+i] = bias[i*64 + j]
// Block tile 128(M) x 64(N), K=64 single pass. 8 warps, 16x64 strip each.
// A: row-major smem + ldmatrix.x4. B: Bs[n][k] + ldmatrix.x4 (.row.col pairing).
// y==0 blocks also zero `out`.
// ---------------------------------------------------------------------------
__global__ void __launch_bounds__(256)
proj_kernel(const float* __restrict__ atom,
            const float* __restrict__ kern,
            const float* __restrict__ bias,
            float* __restrict__ out)
{
    __shared__ __align__(16) __half Ah[128 * AH_STRIDE];
    __shared__ __align__(16) __half Bs[64 * BS_STRIDE];

    const int a0  = blockIdx.x * 128;  // 35 blocks
    const int c0g = blockIdx.y * 64;   // 17 blocks
    const int tid = threadIdx.x;

    if (blockIdx.y == 0) {
        float4* oz = (float4*)(out + (size_t)a0 * 64);
        // 128 rows * 64 cols = 8192 floats = 2048 float4
        #pragma unroll
        for (int t = 0; t < 8; t++)
            oz[tid + t * 256] = make_float4(0.f, 0.f, 0.f, 0.f);
    }

    // Fill Ah[r][j] (fp32 -> fp16), gmem coalesced in j
    #pragma unroll
    for (int t = 0; t < 32; t++) {
        int idx = tid + t * 256;
        int r = idx >> 6, j = idx & 63;
        Ah[r * AH_STRIDE + j] = __float2half(atom[(a0 + r) * 64 + j]);
    }
    // Fill Bs[c][j] = W[j][c0g+c], gmem coalesced in j
    #pragma unroll
    for (int t = 0; t < 16; t++) {
        int idx = tid + t * 256;
        int c = idx >> 6, j = idx & 63;
        int gc = c0g + c;
        float w;
        if (gc < 1024) { int kk = gc >> 6, i = gc & 63; w = kern[kk * 4096 + i * 64 + j]; }
        else           { w = bias[(gc - 1024) * 64 + j]; }
        Bs[c * BS_STRIDE + j] = __float2half(w);
    }
    __syncthreads();

    const int wid  = tid >> 5;
    const int lane = tid & 31;
    const int m0   = wid * 16;

    float acc[8][4] = {};   // 8 n-steps of m16n8 fragments

    // A ldmatrix.x4 lane address: row = m0 + (lane&15), col-block = ((lane>>4)<<3)
    const uint32_t a_base =
        smem_u32(&Ah[(m0 + (lane & 15)) * AH_STRIDE + ((lane >> 4) << 3)]);
    // B ldmatrix.x4 lane address: row = ((lane>>4)<<3) + (lane&7) (+ nss*16),
    //                             col-block = (((lane>>3)&1)<<3)
    const uint32_t b_base =
        smem_u32(&Bs[(((lane >> 4) << 3) + (lane & 7)) * BS_STRIDE +
                     (((lane >> 3) & 1) << 3)]);

    #pragma unroll
    for (int ks = 0; ks < 4; ks++) {
        uint32_t A0, A1, A2, A3;
        ldm_x4(A0, A1, A2, A3, a_base + ks * 32);   // 16 halves = 32 B per k-step
        #pragma unroll
        for (int nss = 0; nss < 4; nss++) {
            uint32_t B0, B1, B2, B3;
            ldm_x4(B0, B1, B2, B3,
                   b_base + nss * 16 * BS_STRIDE * 2 + ks * 32);
            mma16816(acc[2 * nss],     A0, A1, A2, A3, B0, B1);
            mma16816(acc[2 * nss + 1], A0, A1, A2, A3, B2, B3);
        }
    }

    // Epilogue: c0,c1 -> (row lane/4, cols 2*(lane&3)); c2,c3 -> row+8
    const int r  = lane >> 2;
    const int cp = (lane & 3) * 2;
    #pragma unroll
    for (int s = 0; s < 8; s++) {
        const int col = c0g + s * 8 + cp;
        const size_t row0 = (size_t)(a0 + m0 + r);
        *(__half2*)&g_Yh[row0 * NCOLS + col]       = __floats2half2_rn(acc[s][0], acc[s][1]);
        *(__half2*)&g_Yh[(row0 + 8) * NCOLS + col] = __floats2half2_rn(acc[s][2], acc[s][3]);
    }
}

// ---------------------------------------------------------------------------
// Phase 2: half-warp per edge (unchanged from R5; validated 14us).
// ---------------------------------------------------------------------------
__global__ void __launch_bounds__(256)
edge_kernel(const float* __restrict__ bond,
            const int* __restrict__ pair,
            float* __restrict__ out)
{
    const int warp = blockIdx.x * 8 + (threadIdx.x >> 5);
    const int half = (threadIdx.x >> 4) & 1;
    const int lid  = threadIdx.x & 15;
    const int e = warp * 2 + half;

    const int2 pr = ((const int2*)pair)[e];
    const int dst = pr.x;
    const int src = pr.y;

    const float4* __restrict__ bp = (const float4*)(bond + (size_t)e * 16);
    const float4 q0 = __ldg(bp + 0);
    const float4 q1 = __ldg(bp + 1);
    const float4 q2 = __ldg(bp + 2);
    const float4 q3 = __ldg(bp + 3);
    const float bk[16] = {q0.x, q0.y, q0.z, q0.w,
                          q1.x, q1.y, q1.z, q1.w,
                          q2.x, q2.y, q2.z, q2.w,
                          q3.x, q3.y, q3.z, q3.w};

    const __half* __restrict__ y = g_Yh + (size_t)src * NCOLS + 4 * lid;

    float m0, m1, m2, m3;
    {
        const uint2 v = *(const uint2*)(y + 1024);
        const float2 flo = __half22float2(*(const __half2*)&v.x);
        const float2 fhi = __half22float2(*(const __half2*)&v.y);
        m0 = flo.x; m1 = flo.y; m2 = fhi.x; m3 = fhi.y;
    }

    #pragma unroll
    for (int k = 0; k < 16; k++) {
        const uint2 v = *(const uint2*)(y + k * 64);
        const float2 flo = __half22float2(*(const __half2*)&v.x);
        const float2 fhi = __half22float2(*(const __half2*)&v.y);
        const float b = bk[k];
        m0 = fmaf(b, flo.x, m0);
        m1 = fmaf(b, flo.y, m1);
        m2 = fmaf(b, fhi.x, m2);
        m3 = fmaf(b, fhi.y, m3);
    }

    float* o = out + (size_t)dst * 64 + 4 * lid;
    asm volatile("red.global.add.v4.f32 [%0], {%1, %2, %3, %4};"
                 :: "l"(o), "f"(m0), "f"(m1), "f"(m2), "f"(m3)
                 : "memory");
}

extern "C" void kernel_launch(void* const* d_in, const int* in_sizes, int n_in,
                              void* d_out, int out_size)
{
    const float* atom = (const float*)d_in[0];      // [4480, 64]
    const float* bond = (const float*)d_in[1];      // [65536, 16]
    const int*   pair = (const int*)d_in[2];        // [65536, 2] int32
    const float* kern = (const float*)d_in[3];      // [16, 4096]
    const float* bias = (const float*)d_in[4];      // [4096]
    float*       out  = (float*)d_out;              // [4480, 64]

    (void)in_sizes; (void)n_in; (void)out_size;

    dim3 grid1(NUM_SEGMENTS / 128, 17);  // (35, 17); y==0 blocks zero `out`
    proj_kernel<<<grid1, 256>>>(atom, kern, bias, out);

    edge_kernel<<<N_EDGES / 16, 256>>>(bond, pair, out);
}